// round 1
// baseline (speedup 1.0000x reference)
#include <cuda_runtime.h>
#include <cstdint>

#define BATCH 32
#define NPTS  2048
#define DIM   16
#define TILE  64
#define BIG2  1.0e16f
#define HUGEV 1.0e30f

// ---------------- scratch (no allocs allowed) ----------------
__device__ float g_cA[BATCH * NPTS * DIM];   // compacted valid outputs
__device__ float g_cB[BATCH * NPTS * DIM];   // compacted valid targets
__device__ float g_wA[BATCH * NPTS];         // weights of valid outputs
__device__ float g_wB[BATCH * NPTS];         // weights of valid targets
__device__ int   g_cntA[BATCH];
__device__ int   g_cntB[BATCH];
__device__ int   g_colmin[BATCH * NPTS];     // float-as-int (nonneg) min over n

// ---------------- init ----------------
__global__ void init_kernel(float* out) {
    int t = blockIdx.x * blockDim.x + threadIdx.x;
    int stride = gridDim.x * blockDim.x;
    for (int i = t; i < BATCH * NPTS; i += stride) g_colmin[i] = 0x7F800000; // +inf
    if (t < BATCH) { g_cntA[t] = 0; g_cntB[t] = 0; out[t] = 0.0f; }
}

// ---------------- compaction ----------------
__global__ void compact_kernel(const float* __restrict__ ow, const float* __restrict__ pts_o,
                               const float* __restrict__ tw, const float* __restrict__ pts_t) {
    int b   = blockIdx.x >> 1;
    int sel = blockIdx.x & 1;
    const float* w   = sel ? tw    : ow;
    const float* pts = sel ? pts_t : pts_o;
    float* dstP = sel ? g_cB : g_cA;
    float* dstW = sel ? g_wB : g_wA;
    int*   cnt  = sel ? g_cntB : g_cntA;

    for (int i = threadIdx.x; i < NPTS; i += blockDim.x) {
        float wv = w[b * NPTS + i];
        if (wv != 0.0f) {
            int pos = atomicAdd(&cnt[b], 1);
            const float4* s = (const float4*)(pts + (size_t)(b * NPTS + i) * DIM);
            float4* d = (float4*)(dstP + (size_t)(b * NPTS + pos) * DIM);
            d[0] = s[0]; d[1] = s[1]; d[2] = s[2]; d[3] = s[3];
            dstW[b * NPTS + pos] = wv;
        }
    }
}

// ---------------- pair kernel: 64x64 tile, 4x4 per thread ----------------
// smem row stride of 20 floats: conflict-free LDS.128 for tx-strided column loads.
#define SROW 20

__global__ __launch_bounds__(256) void pair_kernel(float* out) {
    int b  = blockIdx.y;
    int Nv = g_cntA[b];
    int Mv = g_cntB[b];
    int n0 = blockIdx.x * TILE;
    if (n0 >= Nv) return;

    __shared__ float As[TILE * SROW];
    __shared__ float Bs[TILE * SROW];
    __shared__ float sq4[TILE * 4];
    __shared__ float asq[TILE];
    __shared__ float bsq[TILE];
    __shared__ float csh[8 * TILE];

    int tid  = threadIdx.x;
    int tx   = tid & 15;
    int ty   = tid >> 4;
    int lane = tid & 31;
    int wrp  = tid >> 5;

    // ---- load A tile (64 rows x 16 floats), per-chunk squared norms ----
    {
        int row = tid >> 2, q = tid & 3;
        float4 v = make_float4(0.f, 0.f, 0.f, 0.f);
        int g = n0 + row;
        if (g < Nv) v = ((const float4*)(g_cA + (size_t)(b * NPTS + g) * DIM))[q];
        ((float4*)(As + row * SROW))[q] = v;
        sq4[row * 4 + q] = v.x * v.x + v.y * v.y + v.z * v.z + v.w * v.w;
    }
    __syncthreads();
    if (tid < TILE) {
        asq[tid] = (n0 + tid < Nv)
                 ? (sq4[tid*4] + sq4[tid*4+1] + sq4[tid*4+2] + sq4[tid*4+3])
                 : HUGEV;
    }

    float rowmin[4] = {HUGEV, HUGEV, HUGEV, HUGEV};
    int mtiles = (Mv + TILE - 1) / TILE;

    for (int mt = 0; mt < mtiles; mt++) {
        int m0 = mt * TILE;
        __syncthreads();  // prior readers of Bs/sq4/csh done; first iter: asq visible

        // ---- load B tile ----
        {
            int row = tid >> 2, q = tid & 3;
            float4 v = make_float4(0.f, 0.f, 0.f, 0.f);
            int g = m0 + row;
            if (g < Mv) v = ((const float4*)(g_cB + (size_t)(b * NPTS + g) * DIM))[q];
            ((float4*)(Bs + row * SROW))[q] = v;
            sq4[row * 4 + q] = v.x * v.x + v.y * v.y + v.z * v.z + v.w * v.w;
        }
        __syncthreads();
        if (tid < TILE) {
            bsq[tid] = (m0 + tid < Mv)
                     ? (sq4[tid*4] + sq4[tid*4+1] + sq4[tid*4+2] + sq4[tid*4+3])
                     : HUGEV;
        }
        __syncthreads();

        // ---- dot products: acc[ii][jj] = a_i . b_j ----
        float acc[4][4];
        #pragma unroll
        for (int ii = 0; ii < 4; ii++)
            #pragma unroll
            for (int jj = 0; jj < 4; jj++) acc[ii][jj] = 0.0f;

        #pragma unroll
        for (int kq = 0; kq < 4; kq++) {
            float4 a4[4], b4[4];
            #pragma unroll
            for (int ii = 0; ii < 4; ii++)
                a4[ii] = ((const float4*)(As + (ii * 16 + ty) * SROW))[kq];
            #pragma unroll
            for (int jj = 0; jj < 4; jj++)
                b4[jj] = ((const float4*)(Bs + (jj * 16 + tx) * SROW))[kq];
            #pragma unroll
            for (int ii = 0; ii < 4; ii++)
                #pragma unroll
                for (int jj = 0; jj < 4; jj++) {
                    acc[ii][jj] = fmaf(a4[ii].x, b4[jj].x, acc[ii][jj]);
                    acc[ii][jj] = fmaf(a4[ii].y, b4[jj].y, acc[ii][jj]);
                    acc[ii][jj] = fmaf(a4[ii].z, b4[jj].z, acc[ii][jj]);
                    acc[ii][jj] = fmaf(a4[ii].w, b4[jj].w, acc[ii][jj]);
                }
        }

        // ---- epilogue: d2 = asq + bsq - 2*dot; row/col mins ----
        float aq[4], bq[4];
        #pragma unroll
        for (int ii = 0; ii < 4; ii++) aq[ii] = asq[ii * 16 + ty];
        #pragma unroll
        for (int jj = 0; jj < 4; jj++) bq[jj] = bsq[jj * 16 + tx];

        float cm[4] = {HUGEV, HUGEV, HUGEV, HUGEV};
        #pragma unroll
        for (int ii = 0; ii < 4; ii++) {
            float rm = HUGEV;
            #pragma unroll
            for (int jj = 0; jj < 4; jj++) {
                float d2 = fmaf(-2.0f, acc[ii][jj], aq[ii] + bq[jj]);
                rm = fminf(rm, d2);
                cm[jj] = fminf(cm[jj], d2);
            }
            rowmin[ii] = fminf(rowmin[ii], rm);
        }

        // ---- col-min: reduce across ty pair in warp, then across 8 warps ----
        #pragma unroll
        for (int jj = 0; jj < 4; jj++) {
            float v = fmaxf(cm[jj], 0.0f);  // clamp => int-ordered atomicMin valid
            v = fminf(v, __shfl_xor_sync(0xFFFFFFFFu, v, 16));
            if (lane < 16) csh[wrp * TILE + jj * 16 + tx] = v;
        }
        __syncthreads();
        if (tid < TILE && (m0 + tid) < Mv) {
            float v = csh[tid];
            #pragma unroll
            for (int w2 = 1; w2 < 8; w2++) v = fminf(v, csh[w2 * TILE + tid]);
            atomicMin(&g_colmin[b * NPTS + m0 + tid], __float_as_int(v));
        }
    }

    // ---- row-min: reduce across tx (lane bits 0..3), accumulate to out[b] ----
    #pragma unroll
    for (int ii = 0; ii < 4; ii++) {
        float r = rowmin[ii];
        r = fminf(r, __shfl_xor_sync(0xFFFFFFFFu, r, 1));
        r = fminf(r, __shfl_xor_sync(0xFFFFFFFFu, r, 2));
        r = fminf(r, __shfl_xor_sync(0xFFFFFFFFu, r, 4));
        r = fminf(r, __shfl_xor_sync(0xFFFFFFFFu, r, 8));
        rowmin[ii] = r;
    }
    if (tx == 0) {
        float contrib = 0.0f;
        #pragma unroll
        for (int ii = 0; ii < 4; ii++) {
            int g = n0 + ii * 16 + ty;
            if (g < Nv) {
                float r = rowmin[ii];
                float v = (r >= 1e29f) ? BIG2 : fmaxf(r, 0.0f);
                contrib += v * g_wA[b * NPTS + g];
            }
        }
        atomicAdd(&out[b], contrib);
    }
}

// ---------------- finalize: sum col mins * t_weights ----------------
__global__ void finalize_kernel(float* out) {
    int b  = blockIdx.x;
    int Mv = g_cntB[b];
    __shared__ float red[256];
    float s = 0.0f;
    for (int m = threadIdx.x; m < Mv; m += 256) {
        float v = __int_as_float(g_colmin[b * NPTS + m]);
        v = (v >= 1e29f) ? BIG2 : v;   // +inf sentinel (no valid n) -> BIG^2
        s += v * g_wB[b * NPTS + m];
    }
    red[threadIdx.x] = s;
    __syncthreads();
    for (int step = 128; step > 0; step >>= 1) {
        if (threadIdx.x < step) red[threadIdx.x] += red[threadIdx.x + step];
        __syncthreads();
    }
    if (threadIdx.x == 0) out[b] += red[0];
}

// ---------------- launch ----------------
extern "C" void kernel_launch(void* const* d_in, const int* in_sizes, int n_in,
                              void* d_out, int out_size) {
    const float* ow  = (const float*)d_in[0];  // [B, N]
    const float* op  = (const float*)d_in[1];  // [B, N, D]
    const float* tw  = (const float*)d_in[2];  // [B, M]
    const float* tp  = (const float*)d_in[3];  // [B, M, D]
    float* out = (float*)d_out;                // [B]

    init_kernel<<<64, 256>>>(out);
    compact_kernel<<<2 * BATCH, 256>>>(ow, op, tw, tp);
    dim3 grid(NPTS / TILE, BATCH);
    pair_kernel<<<grid, 256>>>(out);
    finalize_kernel<<<BATCH, 256>>>(out);
}

// round 3
// speedup vs baseline: 1.3530x; 1.3530x over previous
#include <cuda_runtime.h>
#include <cstdint>

#define BATCH 32
#define NPTS  2048
#define DIM   16
#define TN    128
#define TM    64
#define SROW  20
#define BIG2  1.0e16f
#define HUGEV 1.0e30f

// ---------------- scratch (no allocs allowed) ----------------
__device__ float g_cA[BATCH * NPTS * DIM];
__device__ float g_cB[BATCH * NPTS * DIM];
__device__ float g_wA[BATCH * NPTS];
__device__ float g_wB[BATCH * NPTS];
__device__ int   g_cntA[BATCH];
__device__ int   g_cntB[BATCH];
__device__ int   g_colmin[BATCH * NPTS];   // float-as-int (nonneg), +inf init
__device__ int   g_done[BATCH];

// ---------------- setup: init + prefix-scan compaction (no atomics) --------
__global__ __launch_bounds__(256) void setup_kernel(
    const float* __restrict__ ow, const float* __restrict__ op,
    const float* __restrict__ tw, const float* __restrict__ tp,
    float* out) {
    int blk = blockIdx.x;              // 64 blocks: (b, sel)
    int b   = blk >> 1;
    int sel = blk & 1;
    int tid = threadIdx.x, lane = tid & 31, wrp = tid >> 5;

    // init a 1024-slice of colmin; reset out/done
    int base = blk * 1024;
    for (int i = tid; i < 1024; i += 256) g_colmin[base + i] = 0x7F800000;
    if (sel == 0 && tid == 0) { out[b] = 0.0f; g_done[b] = 0; }

    const float* w   = sel ? tw    : ow;
    const float* pts = sel ? tp    : op;
    float* dstP = sel ? g_cB : g_cA;
    float* dstW = sel ? g_wB : g_wA;
    int*   cnt  = sel ? g_cntB : g_cntA;

    // each thread owns 8 contiguous items
    int i0 = tid * 8;
    float wv[8];
    int c = 0;
    #pragma unroll
    for (int k = 0; k < 8; k++) {
        wv[k] = w[b * NPTS + i0 + k];
        c += (wv[k] != 0.0f);
    }
    // warp inclusive scan of per-thread counts
    int incl = c;
    #pragma unroll
    for (int d = 1; d < 32; d <<= 1) {
        int n = __shfl_up_sync(0xFFFFFFFFu, incl, d);
        if (lane >= d) incl += n;
    }
    __shared__ int wtot[8], wbase[8];
    if (lane == 31) wtot[wrp] = incl;
    __syncthreads();
    if (tid == 0) {
        int s = 0;
        #pragma unroll
        for (int wI = 0; wI < 8; wI++) { wbase[wI] = s; s += wtot[wI]; }
        cnt[b] = s;
    }
    __syncthreads();
    int p = wbase[wrp] + incl - c;   // exclusive prefix for this thread
    #pragma unroll
    for (int k = 0; k < 8; k++) {
        if (wv[k] != 0.0f) {
            const float4* s4 = (const float4*)(pts + ((size_t)b * NPTS + i0 + k) * DIM);
            float4* d4 = (float4*)(dstP + ((size_t)b * NPTS + p) * DIM);
            d4[0] = s4[0]; d4[1] = s4[1]; d4[2] = s4[2]; d4[3] = s4[3];
            dstW[b * NPTS + p] = wv[k];
            p++;
        }
    }
}

// ---------------- pair kernel: 128x64 tile, 8x4 per thread ----------------
__global__ __launch_bounds__(256, 2) void pair_kernel(float* out) {
    int b  = blockIdx.y;
    int Nv = g_cntA[b];
    int Mv = g_cntB[b];
    int active = (Nv + TN - 1) / TN;
    if (active < 1) active = 1;        // block 0 always runs (handles Nv==0)
    int bx = blockIdx.x;
    if (bx >= active) return;
    int n0 = bx * TN;

    __shared__ float As[TN * SROW];
    __shared__ float Bs[TM * SROW];
    __shared__ float sq4[TN * 4];
    __shared__ float asq[TN];
    __shared__ float bsq[TM];
    __shared__ float csh[8 * TM];
    __shared__ int   s_last;

    int tid  = threadIdx.x;
    int tx   = tid & 15;      // m direction (4 cols: jj*16+tx)
    int ty   = tid >> 4;      // n direction (8 rows: ii*16+ty)
    int lane = tid & 31;
    int wrp  = tid >> 5;

    // ---- load A tile (128 rows x 16), per-chunk squared norms ----
    for (int i = tid; i < TN * 4; i += 256) {
        int row = i >> 2, q = i & 3;
        float4 v = make_float4(0.f, 0.f, 0.f, 0.f);
        int g = n0 + row;
        if (g < Nv) v = ((const float4*)(g_cA + ((size_t)b * NPTS + g) * DIM))[q];
        ((float4*)(As + row * SROW))[q] = v;
        sq4[i] = v.x * v.x + v.y * v.y + v.z * v.z + v.w * v.w;
    }
    __syncthreads();
    for (int i = tid; i < TN; i += 256)
        asq[i] = (n0 + i < Nv)
               ? (sq4[4*i] + sq4[4*i+1] + sq4[4*i+2] + sq4[4*i+3]) : HUGEV;

    float rowmin[8];
    #pragma unroll
    for (int ii = 0; ii < 8; ii++) rowmin[ii] = HUGEV;

    int mtiles = (Mv + TM - 1) / TM;
    for (int mt = 0; mt < mtiles; mt++) {
        int m0 = mt * TM;
        __syncthreads();   // prior readers of Bs/sq4/csh done; asq visible

        if (tid < TM * 4) {
            int row = tid >> 2, q = tid & 3;
            float4 v = make_float4(0.f, 0.f, 0.f, 0.f);
            int g = m0 + row;
            if (g < Mv) v = ((const float4*)(g_cB + ((size_t)b * NPTS + g) * DIM))[q];
            ((float4*)(Bs + row * SROW))[q] = v;
            sq4[tid] = v.x * v.x + v.y * v.y + v.z * v.z + v.w * v.w;
        }
        __syncthreads();
        if (tid < TM)
            bsq[tid] = (m0 + tid < Mv)
                     ? (sq4[4*tid] + sq4[4*tid+1] + sq4[4*tid+2] + sq4[4*tid+3]) : HUGEV;
        __syncthreads();

        // ---- dots: acc[ii][jj] = a_(ii*16+ty) . b_(jj*16+tx) ----
        float acc[8][4];
        #pragma unroll
        for (int ii = 0; ii < 8; ii++)
            #pragma unroll
            for (int jj = 0; jj < 4; jj++) acc[ii][jj] = 0.0f;

        #pragma unroll
        for (int kq = 0; kq < 4; kq++) {
            float4 a4[8], b4[4];
            #pragma unroll
            for (int ii = 0; ii < 8; ii++)
                a4[ii] = ((const float4*)(As + (ii * 16 + ty) * SROW))[kq];
            #pragma unroll
            for (int jj = 0; jj < 4; jj++)
                b4[jj] = ((const float4*)(Bs + (jj * 16 + tx) * SROW))[kq];
            #pragma unroll
            for (int ii = 0; ii < 8; ii++)
                #pragma unroll
                for (int jj = 0; jj < 4; jj++) {
                    acc[ii][jj] = fmaf(a4[ii].x, b4[jj].x, acc[ii][jj]);
                    acc[ii][jj] = fmaf(a4[ii].y, b4[jj].y, acc[ii][jj]);
                    acc[ii][jj] = fmaf(a4[ii].z, b4[jj].z, acc[ii][jj]);
                    acc[ii][jj] = fmaf(a4[ii].w, b4[jj].w, acc[ii][jj]);
                }
        }

        // ---- epilogue: d2 + row/col mins ----
        float aq[8], bq[4];
        #pragma unroll
        for (int ii = 0; ii < 8; ii++) aq[ii] = asq[ii * 16 + ty];
        #pragma unroll
        for (int jj = 0; jj < 4; jj++) bq[jj] = bsq[jj * 16 + tx];

        float cm[4] = {HUGEV, HUGEV, HUGEV, HUGEV};
        #pragma unroll
        for (int ii = 0; ii < 8; ii++) {
            float rm = HUGEV;
            #pragma unroll
            for (int jj = 0; jj < 4; jj++) {
                float d2 = fmaf(-2.0f, acc[ii][jj], aq[ii] + bq[jj]);
                rm = fminf(rm, d2);
                cm[jj] = fminf(cm[jj], d2);
            }
            rowmin[ii] = fminf(rowmin[ii], rm);
        }

        // ---- col-min: shfl across ty-pair, smem across 8 warps, atomicMin --
        #pragma unroll
        for (int jj = 0; jj < 4; jj++) {
            float v = fmaxf(cm[jj], 0.0f);   // clamp -> int-ordered atomicMin
            v = fminf(v, __shfl_xor_sync(0xFFFFFFFFu, v, 16));
            if (lane < 16) csh[wrp * TM + jj * 16 + tx] = v;
        }
        __syncthreads();
        if (tid < TM) {
            float v = csh[tid];
            #pragma unroll
            for (int w2 = 1; w2 < 8; w2++) v = fminf(v, csh[w2 * TM + tid]);
            atomicMin(&g_colmin[b * NPTS + m0 + tid], __float_as_int(v));
        }
    }

    // ---- row-min reduction over tx lanes (xor 1,2,4,8) ----
    #pragma unroll
    for (int ii = 0; ii < 8; ii++) {
        float r = rowmin[ii];
        r = fminf(r, __shfl_xor_sync(0xFFFFFFFFu, r, 1));
        r = fminf(r, __shfl_xor_sync(0xFFFFFFFFu, r, 2));
        r = fminf(r, __shfl_xor_sync(0xFFFFFFFFu, r, 4));
        r = fminf(r, __shfl_xor_sync(0xFFFFFFFFu, r, 8));
        rowmin[ii] = r;
    }
    if (tx == 0) {
        float contrib = 0.0f;
        #pragma unroll
        for (int ii = 0; ii < 8; ii++) {
            int g = n0 + ii * 16 + ty;
            if (g < Nv) {
                float r = rowmin[ii];
                float v = (r >= 1e29f) ? BIG2 : fmaxf(r, 0.0f);
                contrib += v * g_wA[b * NPTS + g];
            }
        }
        atomicAdd(&out[b], contrib);
    }

    // ---- last block of this batch finalizes the column mins ----
    __threadfence();
    __syncthreads();
    if (tid == 0)
        s_last = (atomicAdd(&g_done[b], 1) == active - 1) ? 1 : 0;
    __syncthreads();
    if (s_last) {
        float s = 0.0f;
        for (int m = tid; m < Mv; m += 256) {
            float v = __int_as_float(__ldcg(&g_colmin[b * NPTS + m]));
            v = (v >= 1e29f) ? BIG2 : v;
            s += v * g_wB[b * NPTS + m];
        }
        #pragma unroll
        for (int d = 16; d > 0; d >>= 1)
            s += __shfl_xor_sync(0xFFFFFFFFu, s, d);
        if (lane == 0) atomicAdd(&out[b], s);
    }
}

// ---------------- launch ----------------
extern "C" void kernel_launch(void* const* d_in, const int* in_sizes, int n_in,
                              void* d_out, int out_size) {
    const float* ow = (const float*)d_in[0];  // [B, N]
    const float* op = (const float*)d_in[1];  // [B, N, D]
    const float* tw = (const float*)d_in[2];  // [B, M]
    const float* tp = (const float*)d_in[3];  // [B, M, D]
    float* out = (float*)d_out;               // [B]

    setup_kernel<<<2 * BATCH, 256>>>(ow, op, tw, tp, out);
    dim3 grid(NPTS / TN, BATCH);
    pair_kernel<<<grid, 256>>>(out);
}

// round 4
// speedup vs baseline: 1.5144x; 1.1192x over previous
#include <cuda_runtime.h>
#include <cstdint>

#define BATCH 32
#define NPTS  2048
#define DIM   16
#define TN    128
#define TM    128
#define KST   132            // transposed smem row stride (floats), 16B-aligned
#define BIG2  1.0e16f
#define HUGEV 1.0e30f

typedef unsigned long long ull;

// ---------------- scratch (no allocs allowed) ----------------
__device__ float g_cA[BATCH * NPTS * DIM];
__device__ float g_cB[BATCH * NPTS * DIM];
__device__ float g_wA[BATCH * NPTS];
__device__ float g_wB[BATCH * NPTS];
__device__ int   g_cntA[BATCH];
__device__ int   g_cntB[BATCH];
__device__ int   g_colmin[BATCH * NPTS];   // float-as-int (nonneg), +inf init
__device__ int   g_done[BATCH];

// ---------------- packed f32x2 helpers ----------------
__device__ __forceinline__ void fma2(ull& d, ull a, ull b) {
    asm("fma.rn.f32x2 %0, %1, %2, %0;" : "+l"(d) : "l"(a), "l"(b));
}
__device__ __forceinline__ ull fma2v(ull a, ull b, ull c) {
    ull d; asm("fma.rn.f32x2 %0, %1, %2, %3;" : "=l"(d) : "l"(a), "l"(b), "l"(c));
    return d;
}
__device__ __forceinline__ ull add2(ull a, ull b) {
    ull d; asm("add.rn.f32x2 %0, %1, %2;" : "=l"(d) : "l"(a), "l"(b));
    return d;
}
__device__ __forceinline__ ull bcast2(float x) {
    ull d; asm("mov.b64 %0, {%1, %1};" : "=l"(d) : "f"(x));
    return d;
}
__device__ __forceinline__ void unpack2(ull v, float& lo, float& hi) {
    asm("mov.b64 {%0, %1}, %2;" : "=f"(lo), "=f"(hi) : "l"(v));
}

// ---------------- setup: init + prefix-scan compaction ----------------
__global__ __launch_bounds__(256) void setup_kernel(
    const float* __restrict__ ow, const float* __restrict__ op,
    const float* __restrict__ tw, const float* __restrict__ tp,
    float* out) {
    int blk = blockIdx.x;              // 64 blocks: (b, sel)
    int b   = blk >> 1;
    int sel = blk & 1;
    int tid = threadIdx.x, lane = tid & 31, wrp = tid >> 5;

    int base = blk * 1024;
    for (int i = tid; i < 1024; i += 256) g_colmin[base + i] = 0x7F800000;
    if (sel == 0 && tid == 0) { out[b] = 0.0f; g_done[b] = 0; }

    const float* w   = sel ? tw : ow;
    const float* pts = sel ? tp : op;
    float* dstP = sel ? g_cB : g_cA;
    float* dstW = sel ? g_wB : g_wA;
    int*   cnt  = sel ? g_cntB : g_cntA;

    int i0 = tid * 8;
    float wv[8];
    int c = 0;
    #pragma unroll
    for (int k = 0; k < 8; k++) {
        wv[k] = w[b * NPTS + i0 + k];
        c += (wv[k] != 0.0f);
    }
    int incl = c;
    #pragma unroll
    for (int d = 1; d < 32; d <<= 1) {
        int n = __shfl_up_sync(0xFFFFFFFFu, incl, d);
        if (lane >= d) incl += n;
    }
    __shared__ int wtot[8], wbase[8];
    if (lane == 31) wtot[wrp] = incl;
    __syncthreads();
    if (tid == 0) {
        int s = 0;
        #pragma unroll
        for (int wI = 0; wI < 8; wI++) { wbase[wI] = s; s += wtot[wI]; }
        cnt[b] = s;
    }
    __syncthreads();
    int p = wbase[wrp] + incl - c;
    #pragma unroll
    for (int k = 0; k < 8; k++) {
        if (wv[k] != 0.0f) {
            const float4* s4 = (const float4*)(pts + ((size_t)b * NPTS + i0 + k) * DIM);
            float4* d4 = (float4*)(dstP + ((size_t)b * NPTS + p) * DIM);
            d4[0] = s4[0]; d4[1] = s4[1]; d4[2] = s4[2]; d4[3] = s4[3];
            dstW[b * NPTS + p] = wv[k];
            p++;
        }
    }
}

// ---------------- pair kernel: 128x128 tile, 8x8 frag, f32x2 ----------------
__global__ __launch_bounds__(256, 2) void pair_kernel(float* out) {
    int b  = blockIdx.y;
    int Nv = g_cntA[b];
    int Mv = g_cntB[b];
    int active = (Nv + TN - 1) / TN;
    if (active < 1) active = 1;
    int bx = blockIdx.x;
    if (bx >= active) return;
    int n0 = bx * TN;

    __shared__ __align__(16) float As_t[16 * KST];
    __shared__ __align__(16) float Bs_t[16 * KST];
    __shared__ __align__(16) float asq[TN];
    __shared__ __align__(16) float bsq[TM];
    __shared__ float csh[8 * TM];
    __shared__ int   s_last;

    int tid  = threadIdx.x;
    int tx   = tid & 15;     // col group: cols tx*8 + c
    int ty   = tid >> 4;     // row group: rows ty*8 + r
    int lane = tid & 31;
    int wrp  = tid >> 5;

    // ---- load A (k-transposed) + asq ----
    #pragma unroll
    for (int rep = 0; rep < 2; rep++) {
        int j = tid + rep * 256;            // 0..511
        int row = j >> 2, kq = j & 3;
        int g = n0 + row;
        float4 v = make_float4(0.f, 0.f, 0.f, 0.f);
        if (g < Nv) v = ((const float4*)(g_cA + ((size_t)b * NPTS + g) * DIM))[kq];
        As_t[(4 * kq + 0) * KST + row] = v.x;
        As_t[(4 * kq + 1) * KST + row] = v.y;
        As_t[(4 * kq + 2) * KST + row] = v.z;
        As_t[(4 * kq + 3) * KST + row] = v.w;
        float p = v.x * v.x + v.y * v.y + v.z * v.z + v.w * v.w;
        p += __shfl_xor_sync(0xFFFFFFFFu, p, 1);
        p += __shfl_xor_sync(0xFFFFFFFFu, p, 2);
        if (kq == 0) asq[row] = (g < Nv) ? p : HUGEV;
    }

    float rowmin[8];
    #pragma unroll
    for (int r = 0; r < 8; r++) rowmin[r] = HUGEV;

    int mtiles = (Mv + TM - 1) / TM;
    for (int mt = 0; mt < mtiles; mt++) {
        int m0 = mt * TM;
        __syncthreads();   // prior Bs/csh consumers done; asq visible (1st iter)

        // ---- load B (k-transposed) + bsq ----
        {
            int col = tid >> 1, half = tid & 1;
            int g = m0 + col;
            float4 v0 = make_float4(0.f, 0.f, 0.f, 0.f), v1 = v0;
            if (g < Mv) {
                const float4* p4 = (const float4*)(g_cB + ((size_t)b * NPTS + g) * DIM);
                v0 = p4[2 * half]; v1 = p4[2 * half + 1];
            }
            int k0 = 8 * half;
            Bs_t[(k0 + 0) * KST + col] = v0.x;
            Bs_t[(k0 + 1) * KST + col] = v0.y;
            Bs_t[(k0 + 2) * KST + col] = v0.z;
            Bs_t[(k0 + 3) * KST + col] = v0.w;
            Bs_t[(k0 + 4) * KST + col] = v1.x;
            Bs_t[(k0 + 5) * KST + col] = v1.y;
            Bs_t[(k0 + 6) * KST + col] = v1.z;
            Bs_t[(k0 + 7) * KST + col] = v1.w;
            float p = v0.x * v0.x + v0.y * v0.y + v0.z * v0.z + v0.w * v0.w
                    + v1.x * v1.x + v1.y * v1.y + v1.z * v1.z + v1.w * v1.w;
            p += __shfl_xor_sync(0xFFFFFFFFu, p, 1);
            if (half == 0) bsq[col] = (g < Mv) ? p : HUGEV;
        }
        __syncthreads();

        // ---- mainloop: acc2[p][c] (rows 2p,2p+1) x (col c) packed over rows
        ull acc[4][8];
        #pragma unroll
        for (int p = 0; p < 4; p++)
            #pragma unroll
            for (int c = 0; c < 8; c++) acc[p][c] = 0ull;

        #pragma unroll
        for (int k = 0; k < 16; k++) {
            const float* arow = As_t + k * KST + ty * 8;
            ulonglong2 A0 = *(const ulonglong2*)(arow);
            ulonglong2 A1 = *(const ulonglong2*)(arow + 4);
            const float* brow = Bs_t + k * KST + tx * 8;
            float4 B0 = *(const float4*)(brow);
            float4 B1 = *(const float4*)(brow + 4);
            ull a2[4] = {A0.x, A0.y, A1.x, A1.y};
            float bs[8] = {B0.x, B0.y, B0.z, B0.w, B1.x, B1.y, B1.z, B1.w};
            #pragma unroll
            for (int c = 0; c < 8; c++) {
                ull bb = bcast2(bs[c]);
                #pragma unroll
                for (int p = 0; p < 4; p++) fma2(acc[p][c], a2[p], bb);
            }
        }

        // ---- epilogue: d2 = asq + bsq - 2*dot (packed), row/col mins ----
        ulonglong2 q0 = *(const ulonglong2*)(asq + ty * 8);
        ulonglong2 q1 = *(const ulonglong2*)(asq + ty * 8 + 4);
        ull aq2[4] = {q0.x, q0.y, q1.x, q1.y};
        const ull NEG2 = 0xC0000000C0000000ull;   // (-2.0f, -2.0f)
        float cm[8];
        #pragma unroll
        for (int c = 0; c < 8; c++) cm[c] = HUGEV;
        #pragma unroll
        for (int c = 0; c < 8; c++) {
            ull bb = bcast2(bsq[tx * 8 + c]);
            #pragma unroll
            for (int p = 0; p < 4; p++) {
                ull s2 = add2(aq2[p], bb);
                ull d2 = fma2v(NEG2, acc[p][c], s2);
                float lo, hi;
                unpack2(d2, lo, hi);
                rowmin[2 * p]     = fminf(rowmin[2 * p], lo);
                rowmin[2 * p + 1] = fminf(rowmin[2 * p + 1], hi);
                cm[c] = fminf(cm[c], fminf(lo, hi));
            }
        }

        // ---- col-min: shfl across ty pair, smem across 8 warps, atomicMin --
        #pragma unroll
        for (int c = 0; c < 8; c++) {
            float v = fmaxf(cm[c], 0.0f);   // clamp -> int-ordered atomicMin
            v = fminf(v, __shfl_xor_sync(0xFFFFFFFFu, v, 16));
            if (lane < 16) csh[wrp * TM + tx * 8 + c] = v;
        }
        __syncthreads();
        if (tid < TM) {
            float v = csh[tid];
            #pragma unroll
            for (int w2 = 1; w2 < 8; w2++) v = fminf(v, csh[w2 * TM + tid]);
            if (m0 + tid < Mv)
                atomicMin(&g_colmin[b * NPTS + m0 + tid], __float_as_int(v));
        }
    }

    // ---- row-min reduction over tx lanes (xor 1,2,4,8) ----
    #pragma unroll
    for (int r = 0; r < 8; r++) {
        float v = rowmin[r];
        v = fminf(v, __shfl_xor_sync(0xFFFFFFFFu, v, 1));
        v = fminf(v, __shfl_xor_sync(0xFFFFFFFFu, v, 2));
        v = fminf(v, __shfl_xor_sync(0xFFFFFFFFu, v, 4));
        v = fminf(v, __shfl_xor_sync(0xFFFFFFFFu, v, 8));
        rowmin[r] = v;
    }
    if (tx == 0) {
        float contrib = 0.0f;
        #pragma unroll
        for (int r = 0; r < 8; r++) {
            int g = n0 + ty * 8 + r;
            if (g < Nv) {
                float rv = rowmin[r];
                float val = (rv >= 1e29f) ? BIG2 : fmaxf(rv, 0.0f);
                contrib += val * g_wA[b * NPTS + g];
            }
        }
        atomicAdd(&out[b], contrib);
    }

    // ---- last block of this batch finalizes the column mins ----
    __threadfence();
    __syncthreads();
    if (tid == 0)
        s_last = (atomicAdd(&g_done[b], 1) == active - 1) ? 1 : 0;
    __syncthreads();
    if (s_last) {
        float s = 0.0f;
        for (int m = tid; m < Mv; m += 256) {
            float v = __int_as_float(__ldcg(&g_colmin[b * NPTS + m]));
            v = (v >= 1e29f) ? BIG2 : v;
            s += v * g_wB[b * NPTS + m];
        }
        #pragma unroll
        for (int d = 16; d > 0; d >>= 1)
            s += __shfl_xor_sync(0xFFFFFFFFu, s, d);
        if (lane == 0) atomicAdd(&out[b], s);
    }
}

// ---------------- launch ----------------
extern "C" void kernel_launch(void* const* d_in, const int* in_sizes, int n_in,
                              void* d_out, int out_size) {
    const float* ow = (const float*)d_in[0];  // [B, N]
    const float* op = (const float*)d_in[1];  // [B, N, D]
    const float* tw = (const float*)d_in[2];  // [B, M]
    const float* tp = (const float*)d_in[3];  // [B, M, D]
    float* out = (float*)d_out;               // [B]

    setup_kernel<<<2 * BATCH, 256>>>(ow, op, tw, tp, out);
    dim3 grid(NPTS / TN, BATCH);
    pair_kernel<<<grid, 256>>>(out);
}

// round 5
// speedup vs baseline: 1.5794x; 1.0430x over previous
#include <cuda_runtime.h>
#include <cstdint>

#define BATCH 32
#define NPTS  2048
#define DIM   16
#define TN    128
#define TM    128
#define KST   132            // A transposed row stride (floats)
#define KSTB  144            // B transposed row stride (floats), 4-float gap / 32 cols
#define BIG2  1.0e16f
#define HUGEV 1.0e30f

typedef unsigned long long ull;

// physical column for Bs_t: insert 4-float gap every 32 columns (bank de-conflict)
__device__ __forceinline__ int bpcol(int col) { return col + ((col >> 5) << 2); }

// ---------------- scratch (no allocs allowed) ----------------
__device__ float g_cA[BATCH * NPTS * DIM];
__device__ float g_cB[BATCH * NPTS * DIM];
__device__ float g_wA[BATCH * NPTS];
__device__ float g_wB[BATCH * NPTS];
__device__ int   g_cntA[BATCH];
__device__ int   g_cntB[BATCH];
__device__ int   g_colmin[BATCH * NPTS];   // float-as-int (nonneg), +inf init
__device__ int   g_done[BATCH];

// ---------------- packed f32x2 helpers ----------------
__device__ __forceinline__ void fma2(ull& d, ull a, ull b) {
    asm("fma.rn.f32x2 %0, %1, %2, %0;" : "+l"(d) : "l"(a), "l"(b));
}
__device__ __forceinline__ ull fma2v(ull a, ull b, ull c) {
    ull d; asm("fma.rn.f32x2 %0, %1, %2, %3;" : "=l"(d) : "l"(a), "l"(b), "l"(c));
    return d;
}
__device__ __forceinline__ ull add2(ull a, ull b) {
    ull d; asm("add.rn.f32x2 %0, %1, %2;" : "=l"(d) : "l"(a), "l"(b));
    return d;
}
__device__ __forceinline__ ull bcast2(float x) {
    ull d; asm("mov.b64 %0, {%1, %1};" : "=l"(d) : "f"(x));
    return d;
}
__device__ __forceinline__ void unpack2(ull v, float& lo, float& hi) {
    asm("mov.b64 {%0, %1}, %2;" : "=f"(lo), "=f"(hi) : "l"(v));
}

// ---------------- setup: init + prefix-scan compaction ----------------
__global__ __launch_bounds__(256) void setup_kernel(
    const float* __restrict__ ow, const float* __restrict__ op,
    const float* __restrict__ tw, const float* __restrict__ tp,
    float* out) {
    int blk = blockIdx.x;              // 64 blocks: (b, sel)
    int b   = blk >> 1;
    int sel = blk & 1;
    int tid = threadIdx.x, lane = tid & 31, wrp = tid >> 5;

    int base = blk * 1024;
    for (int i = tid; i < 1024; i += 256) g_colmin[base + i] = 0x7F800000;
    if (sel == 0 && tid == 0) { out[b] = 0.0f; g_done[b] = 0; }

    const float* w   = sel ? tw : ow;
    const float* pts = sel ? tp : op;
    float* dstP = sel ? g_cB : g_cA;
    float* dstW = sel ? g_wB : g_wA;
    int*   cnt  = sel ? g_cntB : g_cntA;

    int i0 = tid * 8;
    float wv[8];
    int c = 0;
    #pragma unroll
    for (int k = 0; k < 8; k++) {
        wv[k] = w[b * NPTS + i0 + k];
        c += (wv[k] != 0.0f);
    }
    int incl = c;
    #pragma unroll
    for (int d = 1; d < 32; d <<= 1) {
        int n = __shfl_up_sync(0xFFFFFFFFu, incl, d);
        if (lane >= d) incl += n;
    }
    __shared__ int wtot[8], wbase[8];
    if (lane == 31) wtot[wrp] = incl;
    __syncthreads();
    if (tid == 0) {
        int s = 0;
        #pragma unroll
        for (int wI = 0; wI < 8; wI++) { wbase[wI] = s; s += wtot[wI]; }
        cnt[b] = s;
    }
    __syncthreads();
    int p = wbase[wrp] + incl - c;
    #pragma unroll
    for (int k = 0; k < 8; k++) {
        if (wv[k] != 0.0f) {
            const float4* s4 = (const float4*)(pts + ((size_t)b * NPTS + i0 + k) * DIM);
            float4* d4 = (float4*)(dstP + ((size_t)b * NPTS + p) * DIM);
            d4[0] = s4[0]; d4[1] = s4[1]; d4[2] = s4[2]; d4[3] = s4[3];
            dstW[b * NPTS + p] = wv[k];
            p++;
        }
    }
}

// ---------------- pair kernel: 128x128 tile, 8x8 frag, f32x2 ----------------
__global__ __launch_bounds__(256, 2) void pair_kernel(float* out) {
    int b  = blockIdx.y;
    int Nv = g_cntA[b];
    int Mv = g_cntB[b];
    int active = (Nv + TN - 1) / TN;
    if (active < 1) active = 1;
    int bx = blockIdx.x;
    if (bx >= active) return;
    int n0 = bx * TN;

    __shared__ __align__(16) float As_t[16 * KST];
    __shared__ __align__(16) float Bs_t[16 * KSTB];
    __shared__ __align__(16) float asq[TN];
    __shared__ __align__(16) float bsq[TM];
    __shared__ float csh[8 * TM];
    __shared__ int   s_last;

    int tid  = threadIdx.x;
    int tx   = tid & 15;     // col group: cols tx*8 + c
    int ty   = tid >> 4;     // row group: rows ty*8 + r
    int lane = tid & 31;
    int wrp  = tid >> 5;
    int bro  = bpcol(tx * 8);   // de-conflicted base of this thread's B cols

    // ---- load A (k-transposed) + asq ----
    #pragma unroll
    for (int rep = 0; rep < 2; rep++) {
        int j = tid + rep * 256;            // 0..511
        int row = j >> 2, kq = j & 3;
        int g = n0 + row;
        float4 v = make_float4(0.f, 0.f, 0.f, 0.f);
        if (g < Nv) v = ((const float4*)(g_cA + ((size_t)b * NPTS + g) * DIM))[kq];
        As_t[(4 * kq + 0) * KST + row] = v.x;
        As_t[(4 * kq + 1) * KST + row] = v.y;
        As_t[(4 * kq + 2) * KST + row] = v.z;
        As_t[(4 * kq + 3) * KST + row] = v.w;
        float p = v.x * v.x + v.y * v.y + v.z * v.z + v.w * v.w;
        p += __shfl_xor_sync(0xFFFFFFFFu, p, 1);
        p += __shfl_xor_sync(0xFFFFFFFFu, p, 2);
        if (kq == 0) asq[row] = (g < Nv) ? p : HUGEV;
    }

    float rowmin[8];
    #pragma unroll
    for (int r = 0; r < 8; r++) rowmin[r] = HUGEV;

    int mtiles = (Mv + TM - 1) / TM;
    for (int mt = 0; mt < mtiles; mt++) {
        int m0 = mt * TM;
        __syncthreads();   // prior Bs/csh consumers done; asq visible (1st iter)

        // ---- load B (k-transposed, de-conflicted cols) + bsq ----
        {
            int col = tid >> 1, half = tid & 1;
            int pc  = bpcol(col);
            int g = m0 + col;
            float4 v0 = make_float4(0.f, 0.f, 0.f, 0.f), v1 = v0;
            if (g < Mv) {
                const float4* p4 = (const float4*)(g_cB + ((size_t)b * NPTS + g) * DIM);
                v0 = p4[2 * half]; v1 = p4[2 * half + 1];
            }
            int k0 = 8 * half;
            Bs_t[(k0 + 0) * KSTB + pc] = v0.x;
            Bs_t[(k0 + 1) * KSTB + pc] = v0.y;
            Bs_t[(k0 + 2) * KSTB + pc] = v0.z;
            Bs_t[(k0 + 3) * KSTB + pc] = v0.w;
            Bs_t[(k0 + 4) * KSTB + pc] = v1.x;
            Bs_t[(k0 + 5) * KSTB + pc] = v1.y;
            Bs_t[(k0 + 6) * KSTB + pc] = v1.z;
            Bs_t[(k0 + 7) * KSTB + pc] = v1.w;
            float p = v0.x * v0.x + v0.y * v0.y + v0.z * v0.z + v0.w * v0.w
                    + v1.x * v1.x + v1.y * v1.y + v1.z * v1.z + v1.w * v1.w;
            p += __shfl_xor_sync(0xFFFFFFFFu, p, 1);
            if (half == 0) bsq[col] = (g < Mv) ? p : HUGEV;
        }
        __syncthreads();

        // ---- mainloop: acc[p][c] = rows(2p,2p+1) x col c, packed over rows
        ull acc[4][8];
        #pragma unroll
        for (int p = 0; p < 4; p++)
            #pragma unroll
            for (int c = 0; c < 8; c++) acc[p][c] = 0ull;

        #pragma unroll
        for (int k = 0; k < 16; k++) {
            const float* arow = As_t + k * KST + ty * 8;
            ulonglong2 A0 = *(const ulonglong2*)(arow);
            ulonglong2 A1 = *(const ulonglong2*)(arow + 4);
            const float* brow = Bs_t + k * KSTB + bro;
            float4 B0 = *(const float4*)(brow);
            float4 B1 = *(const float4*)(brow + 4);
            ull a2[4] = {A0.x, A0.y, A1.x, A1.y};
            float bs[8] = {B0.x, B0.y, B0.z, B0.w, B1.x, B1.y, B1.z, B1.w};
            #pragma unroll
            for (int c = 0; c < 8; c++) {
                ull bb = bcast2(bs[c]);
                #pragma unroll
                for (int p = 0; p < 4; p++) fma2(acc[p][c], a2[p], bb);
            }
        }

        // ---- epilogue: d2 = asq + bsq - 2*dot (packed), row/col mins ----
        ulonglong2 q0 = *(const ulonglong2*)(asq + ty * 8);
        ulonglong2 q1 = *(const ulonglong2*)(asq + ty * 8 + 4);
        ull aq2[4] = {q0.x, q0.y, q1.x, q1.y};
        const ull NEG2 = 0xC0000000C0000000ull;   // (-2.0f, -2.0f)
        float cm[8];
        #pragma unroll
        for (int c = 0; c < 8; c++) cm[c] = HUGEV;
        #pragma unroll
        for (int c = 0; c < 8; c++) {
            ull bb = bcast2(bsq[tx * 8 + c]);
            #pragma unroll
            for (int p = 0; p < 4; p++) {
                ull s2 = add2(aq2[p], bb);
                ull d2 = fma2v(NEG2, acc[p][c], s2);
                float lo, hi;
                unpack2(d2, lo, hi);
                rowmin[2 * p]     = fminf(rowmin[2 * p], lo);
                rowmin[2 * p + 1] = fminf(rowmin[2 * p + 1], hi);
                cm[c] = fminf(cm[c], fminf(lo, hi));
            }
        }

        // ---- col-min: shfl across ty pair, smem across 8 warps, atomicMin --
        #pragma unroll
        for (int c = 0; c < 8; c++) {
            float v = fmaxf(cm[c], 0.0f);   // clamp -> int-ordered atomicMin
            v = fminf(v, __shfl_xor_sync(0xFFFFFFFFu, v, 16));
            if (lane < 16) csh[wrp * TM + tx * 8 + c] = v;
        }
        __syncthreads();
        if (tid < TM) {
            float v = csh[tid];
            #pragma unroll
            for (int w2 = 1; w2 < 8; w2++) v = fminf(v, csh[w2 * TM + tid]);
            if (m0 + tid < Mv)
                atomicMin(&g_colmin[b * NPTS + m0 + tid], __float_as_int(v));
        }
    }

    // ---- row-min reduction over tx lanes (xor 1,2,4,8) ----
    #pragma unroll
    for (int r = 0; r < 8; r++) {
        float v = rowmin[r];
        v = fminf(v, __shfl_xor_sync(0xFFFFFFFFu, v, 1));
        v = fminf(v, __shfl_xor_sync(0xFFFFFFFFu, v, 2));
        v = fminf(v, __shfl_xor_sync(0xFFFFFFFFu, v, 4));
        v = fminf(v, __shfl_xor_sync(0xFFFFFFFFu, v, 8));
        rowmin[r] = v;
    }
    if (tx == 0) {
        float contrib = 0.0f;
        #pragma unroll
        for (int r = 0; r < 8; r++) {
            int g = n0 + ty * 8 + r;
            if (g < Nv) {
                float rv = rowmin[r];
                float val = (rv >= 1e29f) ? BIG2 : fmaxf(rv, 0.0f);
                contrib += val * g_wA[b * NPTS + g];
            }
        }
        atomicAdd(&out[b], contrib);
    }

    // ---- last block of this batch finalizes the column mins ----
    __threadfence();
    __syncthreads();
    if (tid == 0)
        s_last = (atomicAdd(&g_done[b], 1) == active - 1) ? 1 : 0;
    __syncthreads();
    if (s_last) {
        float s = 0.0f;
        for (int m = tid; m < Mv; m += 256) {
            float v = __int_as_float(__ldcg(&g_colmin[b * NPTS + m]));
            v = (v >= 1e29f) ? BIG2 : v;
            s += v * g_wB[b * NPTS + m];
        }
        #pragma unroll
        for (int d = 16; d > 0; d >>= 1)
            s += __shfl_xor_sync(0xFFFFFFFFu, s, d);
        if (lane == 0) atomicAdd(&out[b], s);
    }
}

// ---------------- launch ----------------
extern "C" void kernel_launch(void* const* d_in, const int* in_sizes, int n_in,
                              void* d_out, int out_size) {
    const float* ow = (const float*)d_in[0];  // [B, N]
    const float* op = (const float*)d_in[1];  // [B, N, D]
    const float* tw = (const float*)d_in[2];  // [B, M]
    const float* tp = (const float*)d_in[3];  // [B, M, D]
    float* out = (float*)d_out;               // [B]

    setup_kernel<<<2 * BATCH, 256>>>(ow, op, tw, tp, out);
    dim3 grid(NPTS / TN, BATCH);
    pair_kernel<<<grid, 256>>>(out);
}